// round 9
// baseline (speedup 1.0000x reference)
#include <cuda_runtime.h>
#include <cuda_bf16.h>
#include <cuda_fp16.h>
#include <cstdint>

// Problem constants
#define LQ 1024
#define SQ 1024
#define NBATCH 8
#define EDIM 512
#define BHEADS 64   // NBATCH * HHEADS
#define LGRP 128
#define NGRP 8

// ---------------- scratch (device globals; no allocations allowed) ----------
// packed pair format: uint32 = (hi16) | (lo16 << 16), hi/lo bf16 or fp16
__device__ uint32_t g_qin[LQ * NBATCH * EDIM];      // packed query (bf16 pair)
__device__ uint32_t g_kin[SQ * NBATCH * EDIM];
__device__ uint32_t g_vin[SQ * NBATCH * EDIM];
__device__ uint32_t g_wq[EDIM * EDIM];
__device__ uint32_t g_wk[EDIM * EDIM];
__device__ uint32_t g_wv[EDIM * EDIM];
__device__ uint32_t g_wo[EDIM * EDIM];
__device__ uint32_t g_qp[LQ * NBATCH * EDIM];       // q proj, packed bf16 pair
__device__ uint32_t g_kp[SQ * NBATCH * EDIM];       // k proj, packed bf16 pair
__device__ uint32_t g_vp[SQ * NBATCH * EDIM];       // v proj, packed fp16 pair
__device__ float    g_S[67108864];                  // content scores fp32 (b,l,s)
__device__ __half   g_E[67108864];                  // exp scores fp16 (b,l,s)
__device__ float    g_Z[BHEADS * LQ];               // row sums
__device__ float    g_O[LQ * NBATCH * EDIM];        // numerator fp32 (l, b*64+d)
__device__ uint32_t g_OP[LQ * NBATCH * EDIM];       // normalized out packed bf16 pair

// =================== helpers ================================================
__device__ __forceinline__ uint32_t smem_u32(const void* p) {
    uint32_t a;
    asm("{ .reg .u64 t; cvta.to.shared.u64 t, %1; cvt.u32.u64 %0, t; }" : "=r"(a) : "l"(p));
    return a;
}
__device__ __forceinline__ uint32_t prmt(uint32_t a, uint32_t b, uint32_t sel) {
    uint32_t d;
    asm("prmt.b32 %0, %1, %2, %3;" : "=r"(d) : "r"(a), "r"(b), "r"(sel));
    return d;
}
__device__ __forceinline__ void ldsm_x4(uint32_t* r, uint32_t addr) {
    asm volatile("ldmatrix.sync.aligned.m8n8.x4.shared.b16 {%0,%1,%2,%3}, [%4];"
        : "=r"(r[0]), "=r"(r[1]), "=r"(r[2]), "=r"(r[3]) : "r"(addr));
}
__device__ __forceinline__ void mma_bf16(float* c, const uint32_t* a, const uint32_t* b) {
    asm volatile(
        "mma.sync.aligned.m16n8k16.row.col.f32.bf16.bf16.f32 "
        "{%0,%1,%2,%3}, {%4,%5,%6,%7}, {%8,%9}, {%0,%1,%2,%3};"
        : "+f"(c[0]), "+f"(c[1]), "+f"(c[2]), "+f"(c[3])
        : "r"(a[0]), "r"(a[1]), "r"(a[2]), "r"(a[3]), "r"(b[0]), "r"(b[1]));
}
__device__ __forceinline__ void mma_f16(float* c, const uint32_t* a, const uint32_t* b) {
    asm volatile(
        "mma.sync.aligned.m16n8k16.row.col.f32.f16.f16.f32 "
        "{%0,%1,%2,%3}, {%4,%5,%6,%7}, {%8,%9}, {%0,%1,%2,%3};"
        : "+f"(c[0]), "+f"(c[1]), "+f"(c[2]), "+f"(c[3])
        : "r"(a[0]), "r"(a[1]), "r"(a[2]), "r"(a[3]), "r"(b[0]), "r"(b[1]));
}

// fp32 -> packed (hi|lo<<16)
__device__ __forceinline__ uint32_t packpair_b(float v) {
    __nv_bfloat16 h = __float2bfloat16(v);
    __nv_bfloat16 l = __float2bfloat16(v - __bfloat162float(h));
    return (uint32_t)__bfloat16_as_ushort(h) | ((uint32_t)__bfloat16_as_ushort(l) << 16);
}
__device__ __forceinline__ uint32_t packpair_h(float v) {
    __half h = __float2half_rn(v);
    __half l = __float2half_rn(v - __half2float(h));
    return (uint32_t)__half_as_ushort(h) | ((uint32_t)__half_as_ushort(l) << 16);
}
// fp32 -> (hi,lo) 2-elt splits for streamed operands
__device__ __forceinline__ void split2b(float x, float y, uint32_t& hi, uint32_t& lo) {
    uint32_t px = packpair_b(x), py = packpair_b(y);
    hi = prmt(px, py, 0x5410u);
    lo = prmt(px, py, 0x7632u);
}

// =================== HMMA strided batched GEMM ===============================
// C[z][m][n] = epilogue( sum_k A(m,k)*B(n,k) )
// AMODE: 0 = packed pair uint32 (k contiguous)
//        1 = plain fp16 exact (k contiguous)
// BMODE: 0 = packed pair (BKFAST, k contig)
//        1 = fp32 -> bf16 split (BKFAST, k contig)
//        2 = fp32 -> fp16 split (n contig)
//        3 = packed pair (n contig, scalar extract)
// EPI:   0 = fp32 C = alpha*(acc+bias)
//        1 = EXPZ: e = exp(acc + Cin); fp16 e -> C; atomicAdd rowsum Zp[m*1024+z]
//        3 = DIVZ+PACK: packed-bf16 C = (acc + Cin) / Zp[m*1024+z]
//        4 = PACKB: packed-bf16 C = alpha*(acc+bias)
//        5 = PACKH: packed-fp16 C = alpha*(acc+bias)
// 256 threads = 8 warps (4m x 2n). BK=32. Double-buffered smem. 2 CTAs/SM.
template<int BM, int BN, bool BKFAST, int EPI, int AMODE, int BMODE, bool F16MMA>
__global__ __launch_bounds__(256, 2)
void mma_gemm(const void* __restrict__ Ap, long long aBS, long long aRS,
              const void* __restrict__ Bp, long long bBS, long long bS,
              void* __restrict__ Cp, long long cBS, long long cRS,
              const float* __restrict__ Cin,
              const float* __restrict__ bias, float alpha,
              int K, float* __restrict__ Zp)
{
    constexpr int MT    = BM / 64;
    constexpr int NTL   = BN / 16;
    constexpr int NPAIR = NTL / 2;
    constexpr int ROWB  = 144;
    constexpr int STG   = (BM + BN) * ROWB;
    constexpr int AREGP = BM / 16;                     // 8B loads per thread
    constexpr int BREGP = BKFAST ? BN / 16 : 1;        // 8B loads (BKFAST)
    constexpr int BREGS = BKFAST ? 1 : BN / 8;         // scalar loads (n-contig)

    extern __shared__ __align__(16) char smem[];

    const int tid  = threadIdx.x;
    const int wid  = tid >> 5;
    const int lane = tid & 31;
    const int wm   = wid >> 1;
    const int wn   = wid & 1;
    const int mat  = lane >> 3;
    const int rw   = lane & 7;

    const int tile_n = blockIdx.x * BN;
    const int tile_m = blockIdx.y * BM;
    const int z      = blockIdx.z;

    const uint32_t* AzP = (const uint32_t*)Ap + (long long)z * aBS + (long long)tile_m * aRS;
    const __half*   AzH = (const __half*)Ap   + (long long)z * aBS + (long long)tile_m * aRS;
    const float*    BzF = (const float*)Bp    + (long long)z * bBS;
    const uint32_t* BzP = (const uint32_t*)Bp + (long long)z * bBS;

    float acc[MT][NTL][4];
#pragma unroll
    for (int i = 0; i < MT; i++)
#pragma unroll
        for (int j = 0; j < NTL; j++)
#pragma unroll
            for (int q = 0; q < 4; q++) acc[i][j][q] = 0.0f;

    const uint32_t s_u = smem_u32(smem);
    const uint32_t aAddr0 = s_u + (uint32_t)(wm * (BM / 4) + rw + (mat & 1) * 8) * ROWB
                                + (uint32_t)((mat >> 1) * 16);
    const uint32_t bAddr0 = s_u + (uint32_t)(BM * ROWB)
                                + (uint32_t)(wn * (BN / 2) + rw + (mat >> 1) * 8) * ROWB
                                + (uint32_t)((mat & 1) * 16);

    uint2    aRegP[AREGP];        // AMODE 0: 2 packed elts; AMODE 1: .x only (u32 of 2 halves)
    uint2    bRegP[BREGP];        // BMODE 0 packed pairs
    float2   bRegF[BREGP];        // BMODE 1 fp32 pairs
    float    bRegS[BREGS];        // BMODE 2 scalars
    uint32_t bRegU[BREGS];        // BMODE 3 packed scalars

    auto ldgA = [&](int ch) {
        if (AMODE == 0) {
            const uint32_t* p = AzP + (ch << 5);
#pragma unroll
            for (int j = 0; j < AREGP; j++) {
                int i = tid + j * 256;
                int k2 = i & 15, r = i >> 4;
                aRegP[j] = *reinterpret_cast<const uint2*>(p + (long long)r * aRS + k2 * 2);
            }
        } else {
            const __half* p = AzH + (ch << 5);
#pragma unroll
            for (int j = 0; j < AREGP; j++) {
                int i = tid + j * 256;
                int k2 = i & 15, r = i >> 4;
                aRegP[j].x = *reinterpret_cast<const uint32_t*>(p + (long long)r * aRS + k2 * 2);
            }
        }
    };
    auto stsA = [&](int st) {
        char* base = smem + st * STG;
#pragma unroll
        for (int j = 0; j < AREGP; j++) {
            int i = tid + j * 256;
            int k2 = i & 15, r = i >> 4;
            char* rp = base + r * ROWB + k2 * 4;
            if (AMODE == 0) {
                *reinterpret_cast<uint32_t*>(rp)      = prmt(aRegP[j].x, aRegP[j].y, 0x5410u);
                *reinterpret_cast<uint32_t*>(rp + 64) = prmt(aRegP[j].x, aRegP[j].y, 0x7632u);
            } else {
                *reinterpret_cast<uint32_t*>(rp) = aRegP[j].x;
            }
        }
    };
    auto ldgB = [&](int ch) {
        if (BKFAST) {
            if (BMODE == 0) {
                const uint32_t* p = BzP + (long long)tile_n * bS + (ch << 5);
#pragma unroll
                for (int j = 0; j < BREGP; j++) {
                    int i = tid + j * 256;
                    int k2 = i & 15, r = i >> 4;
                    bRegP[j] = *reinterpret_cast<const uint2*>(p + (long long)r * bS + k2 * 2);
                }
            } else {
                const float* p = BzF + (long long)tile_n * bS + (ch << 5);
#pragma unroll
                for (int j = 0; j < BREGP; j++) {
                    int i = tid + j * 256;
                    int k2 = i & 15, r = i >> 4;
                    bRegF[j] = *reinterpret_cast<const float2*>(p + (long long)r * bS + k2 * 2);
                }
            }
        } else {
            if (BMODE == 3) {
                const uint32_t* p = BzP + tile_n + (long long)(ch << 5) * bS;
#pragma unroll
                for (int j = 0; j < BREGS; j++) {
                    int i = tid + j * 256;
                    int n = i & (BN - 1), k = i / BN;
                    bRegU[j] = p[(long long)k * bS + n];
                }
            } else {
                const float* p = BzF + tile_n + (long long)(ch << 5) * bS;
#pragma unroll
                for (int j = 0; j < BREGS; j++) {
                    int i = tid + j * 256;
                    int n = i & (BN - 1), k = i / BN;
                    bRegS[j] = p[(long long)k * bS + n];
                }
            }
        }
    };
    auto stsB = [&](int st) {
        char* base = smem + st * STG + BM * ROWB;
        if (BKFAST) {
#pragma unroll
            for (int j = 0; j < BREGP; j++) {
                int i = tid + j * 256;
                int k2 = i & 15, r = i >> 4;
                char* rp = base + r * ROWB + k2 * 4;
                uint32_t hi, lo;
                if (BMODE == 0) {
                    hi = prmt(bRegP[j].x, bRegP[j].y, 0x5410u);
                    lo = prmt(bRegP[j].x, bRegP[j].y, 0x7632u);
                } else {
                    split2b(bRegF[j].x, bRegF[j].y, hi, lo);
                }
                *reinterpret_cast<uint32_t*>(rp)      = hi;
                *reinterpret_cast<uint32_t*>(rp + 64) = lo;
            }
        } else {
#pragma unroll
            for (int j = 0; j < BREGS; j++) {
                int i = tid + j * 256;
                int n = i & (BN - 1), k = i / BN;
                unsigned short h, l;
                if (BMODE == 3) {
                    h = (unsigned short)(bRegU[j] & 0xFFFFu);
                    l = (unsigned short)(bRegU[j] >> 16);
                } else {
                    float v = bRegS[j];
                    __half hh = __float2half_rn(v);
                    __half ll = __float2half_rn(v - __half2float(hh));
                    h = __half_as_ushort(hh); l = __half_as_ushort(ll);
                }
                char* rp = base + n * ROWB + k * 2;
                *reinterpret_cast<unsigned short*>(rp)      = h;
                *reinterpret_cast<unsigned short*>(rp + 64) = l;
            }
        }
    };
    auto compute = [&](int st) {
        const uint32_t off = (uint32_t)(st * STG);
#pragma unroll
        for (int ks = 0; ks < 2; ks++) {
            uint32_t aH[MT][4], aL[MT][4];
#pragma unroll
            for (int mt = 0; mt < MT; mt++) {
                uint32_t ad = aAddr0 + off + (uint32_t)(mt * 16 * ROWB) + (uint32_t)(ks * 32);
                ldsm_x4(aH[mt], ad);
                if (!F16MMA) ldsm_x4(aL[mt], ad + 64);
            }
            uint32_t bH[NTL][2], bL[NTL][2];
#pragma unroll
            for (int p = 0; p < NPAIR; p++) {
                uint32_t bd = bAddr0 + off + (uint32_t)(p * 16 * ROWB) + (uint32_t)(ks * 32);
                uint32_t t[4];
                ldsm_x4(t, bd);
                bH[2 * p][0] = t[0]; bH[2 * p][1] = t[1];
                bH[2 * p + 1][0] = t[2]; bH[2 * p + 1][1] = t[3];
                ldsm_x4(t, bd + 64);
                bL[2 * p][0] = t[0]; bL[2 * p][1] = t[1];
                bL[2 * p + 1][0] = t[2]; bL[2 * p + 1][1] = t[3];
            }
#pragma unroll
            for (int mt = 0; mt < MT; mt++)
#pragma unroll
                for (int nt = 0; nt < NTL; nt++) {
                    if (F16MMA) {
                        mma_f16(acc[mt][nt], aH[mt], bH[nt]);
                        mma_f16(acc[mt][nt], aH[mt], bL[nt]);
                    } else {
                        mma_bf16(acc[mt][nt], aH[mt], bH[nt]);
                        mma_bf16(acc[mt][nt], aH[mt], bL[nt]);
                        mma_bf16(acc[mt][nt], aL[mt], bH[nt]);
                    }
                }
        }
    };

    const int nch = K >> 5;
    ldgA(0); ldgB(0);
    stsA(0); stsB(0);
    __syncthreads();
    for (int ch = 0; ch < nch; ch++) {
        const bool more = (ch + 1 < nch);
        if (more) { ldgA(ch + 1); ldgB(ch + 1); }
        compute(ch & 1);
        if (more) {
            stsA((ch + 1) & 1); stsB((ch + 1) & 1);
            __syncthreads();
        }
    }

    // ---- epilogue ----
#pragma unroll
    for (int mt = 0; mt < MT; mt++) {
        int m0 = tile_m + wm * (BM / 4) + mt * 16 + (lane >> 2);
#pragma unroll
        for (int half = 0; half < 2; half++) {
            int m = m0 + half * 8;
            if (EPI == 1) {
                const float* cinrow = Cin + (long long)z * cBS + (long long)m * cRS;
                __half* erow = (__half*)Cp + (long long)z * cBS + (long long)m * cRS;
                float rowsum = 0.0f;
#pragma unroll
                for (int nt = 0; nt < NTL; nt++) {
                    int n = tile_n + wn * (BN / 2) + nt * 8 + (lane & 3) * 2;
                    float2 o = *reinterpret_cast<const float2*>(cinrow + n);
                    float ex = __expf(acc[mt][nt][half * 2]     + o.x);
                    float ey = __expf(acc[mt][nt][half * 2 + 1] + o.y);
                    *reinterpret_cast<__half2*>(erow + n) = __floats2half2_rn(ex, ey);
                    rowsum += ex + ey;
                }
                rowsum += __shfl_xor_sync(0xffffffffu, rowsum, 1);
                rowsum += __shfl_xor_sync(0xffffffffu, rowsum, 2);
                if ((lane & 3) == 0)
                    atomicAdd(&Zp[(long long)m * 1024 + z], rowsum);
            } else if (EPI == 3) {
                const float* cinrow = Cin + (long long)z * cBS + (long long)m * cRS;
                uint32_t* crow = (uint32_t*)Cp + (long long)z * cBS + (long long)m * cRS;
                float invZ = 1.0f / Zp[(long long)m * 1024 + z];
#pragma unroll
                for (int nt = 0; nt < NTL; nt++) {
                    int n = tile_n + wn * (BN / 2) + nt * 8 + (lane & 3) * 2;
                    float2 o = *reinterpret_cast<const float2*>(cinrow + n);
                    uint2 v;
                    v.x = packpair_b((acc[mt][nt][half * 2]     + o.x) * invZ);
                    v.y = packpair_b((acc[mt][nt][half * 2 + 1] + o.y) * invZ);
                    *reinterpret_cast<uint2*>(crow + n) = v;
                }
            } else if (EPI == 4 || EPI == 5) {
                uint32_t* crow = (uint32_t*)Cp + (long long)z * cBS + (long long)m * cRS;
#pragma unroll
                for (int nt = 0; nt < NTL; nt++) {
                    int n = tile_n + wn * (BN / 2) + nt * 8 + (lane & 3) * 2;
                    float vx = acc[mt][nt][half * 2];
                    float vy = acc[mt][nt][half * 2 + 1];
                    if (bias) { vx += bias[n]; vy += bias[n + 1]; }
                    vx *= alpha; vy *= alpha;
                    uint2 v;
                    if (EPI == 4) { v.x = packpair_b(vx); v.y = packpair_b(vy); }
                    else          { v.x = packpair_h(vx); v.y = packpair_h(vy); }
                    *reinterpret_cast<uint2*>(crow + n) = v;
                }
            } else {
                float* crow = (float*)Cp + (long long)z * cBS + (long long)m * cRS;
#pragma unroll
                for (int nt = 0; nt < NTL; nt++) {
                    int n = tile_n + wn * (BN / 2) + nt * 8 + (lane & 3) * 2;
                    float vx = acc[mt][nt][half * 2];
                    float vy = acc[mt][nt][half * 2 + 1];
                    if (bias) { vx += bias[n]; vy += bias[n + 1]; }
                    vx *= alpha; vy *= alpha;
                    float2 v; v.x = vx; v.y = vy;
                    *reinterpret_cast<float2*>(crow + n) = v;
                }
            }
        }
    }
}

// =================== small kernels ===========================================
__global__ __launch_bounds__(256)
void pack_kernel(const float* __restrict__ src, uint32_t* __restrict__ dst)
{
    int i = blockIdx.x * 256 + threadIdx.x;
    dst[i] = packpair_b(src[i]);
}

__global__ __launch_bounds__(256)
void zeroZ_kernel(float* __restrict__ Z)
{
    Z[blockIdx.x * 256 + threadIdx.x] = 0.0f;
}

__global__ __launch_bounds__(256)
void avgw_kernel(const __half* __restrict__ Ebuf, const float* __restrict__ Z,
                 float* __restrict__ out)
{
    int l = blockIdx.x;
    int n = blockIdx.y;
    __shared__ float invZ[8];
    if (threadIdx.x < 8)
        invZ[threadIdx.x] = 0.125f / Z[(n * 8 + threadIdx.x) * 1024 + l];
    __syncthreads();
    int s = threadIdx.x * 4;
    float4 acc = make_float4(0.f, 0.f, 0.f, 0.f);
#pragma unroll
    for (int h = 0; h < 8; h++) {
        const __half2* p = reinterpret_cast<const __half2*>(
            Ebuf + (((long long)(n * 8 + h)) << 20) + (long long)l * 1024 + s);
        float2 a = __half22float2(p[0]);
        float2 b = __half22float2(p[1]);
        float w = invZ[h];
        acc.x += a.x * w; acc.y += a.y * w; acc.z += b.x * w; acc.w += b.y * w;
    }
    *reinterpret_cast<float4*>(
        out + (((long long)n) << 20) + (long long)l * 1024 + s) = acc;
}

// =================== launch ==================================================
extern "C" void kernel_launch(void* const* d_in, const int* in_sizes, int n_in,
                              void* d_out, int out_size)
{
    const float* query = (const float*)d_in[0];
    const float* key   = (const float*)d_in[1];
    const float* value = (const float*)d_in[2];
    const float* pos_k = (const float*)d_in[3];
    const float* pos_v = (const float*)d_in[4];
    const float* Wq = (const float*)d_in[5];
    const float* bq = (const float*)d_in[6];
    const float* Wk = (const float*)d_in[7];
    const float* bk = (const float*)d_in[8];
    const float* Wv = (const float*)d_in[9];
    const float* bv = (const float*)d_in[10];
    const float* Wo = (const float*)d_in[11];
    const float* bo = (const float*)d_in[12];
    float* out = (float*)d_out;

    uint32_t *qin, *kin, *vin, *wq, *wk, *wv, *wo, *qp, *kp, *vp, *OP;
    float *Sbuf, *Zbuf, *Obuf;
    __half* Ebuf;
    cudaGetSymbolAddress((void**)&qin,  g_qin);
    cudaGetSymbolAddress((void**)&kin,  g_kin);
    cudaGetSymbolAddress((void**)&vin,  g_vin);
    cudaGetSymbolAddress((void**)&wq,   g_wq);
    cudaGetSymbolAddress((void**)&wk,   g_wk);
    cudaGetSymbolAddress((void**)&wv,   g_wv);
    cudaGetSymbolAddress((void**)&wo,   g_wo);
    cudaGetSymbolAddress((void**)&qp,   g_qp);
    cudaGetSymbolAddress((void**)&kp,   g_kp);
    cudaGetSymbolAddress((void**)&vp,   g_vp);
    cudaGetSymbolAddress((void**)&OP,   g_OP);
    cudaGetSymbolAddress((void**)&Sbuf, g_S);
    cudaGetSymbolAddress((void**)&Ebuf, g_E);
    cudaGetSymbolAddress((void**)&Zbuf, g_Z);
    cudaGetSymbolAddress((void**)&Obuf, g_O);

    const int SM_128_64 = 2 * (128 + 64) * 144;   // 55296
    const int SM_64_128 = 2 * (64 + 128) * 144;   // 55296
    const int SM_64_64  = 2 * (64 + 64) * 144;    // 36864

    cudaFuncSetAttribute(mma_gemm<128, 64, true, 4, 0, 0, false>,
        cudaFuncAttributeMaxDynamicSharedMemorySize, SM_128_64);
    cudaFuncSetAttribute(mma_gemm<128, 64, true, 5, 0, 0, false>,
        cudaFuncAttributeMaxDynamicSharedMemorySize, SM_128_64);
    cudaFuncSetAttribute(mma_gemm<128, 64, true, 0, 0, 0, false>,
        cudaFuncAttributeMaxDynamicSharedMemorySize, SM_128_64);
    cudaFuncSetAttribute(mma_gemm<64, 128, true, 1, 0, 1, false>,
        cudaFuncAttributeMaxDynamicSharedMemorySize, SM_64_128);
    cudaFuncSetAttribute(mma_gemm<128, 64, false, 0, 1, 3, true>,
        cudaFuncAttributeMaxDynamicSharedMemorySize, SM_128_64);
    cudaFuncSetAttribute(mma_gemm<64, 64, false, 3, 1, 2, true>,
        cudaFuncAttributeMaxDynamicSharedMemorySize, SM_64_64);

    // 0. Pack inputs to pair format + zero Z
    pack_kernel<<<16384, 256>>>(query, qin);
    pack_kernel<<<16384, 256>>>(key,   kin);
    pack_kernel<<<16384, 256>>>(value, vin);
    pack_kernel<<<1024, 256>>>(Wq, wq);
    pack_kernel<<<1024, 256>>>(Wk, wk);
    pack_kernel<<<1024, 256>>>(Wv, wv);
    pack_kernel<<<1024, 256>>>(Wo, wo);
    zeroZ_kernel<<<256, 256>>>(Zbuf);

    // 1-3. Projections (packed in, packed out)
    mma_gemm<128, 64, true, 4, 0, 0, false><<<dim3(8, 64, 1), 256, SM_128_64>>>(
        qin, 0, 512,  wq, 0, 512,  qp, 0, 512,  nullptr, bq, 0.125f, 512, nullptr);
    mma_gemm<128, 64, true, 4, 0, 0, false><<<dim3(8, 64, 1), 256, SM_128_64>>>(
        kin, 0, 512,  wk, 0, 512,  kp, 0, 512,  nullptr, bk, 1.0f, 512, nullptr);
    mma_gemm<128, 64, true, 5, 0, 0, false><<<dim3(8, 64, 1), 256, SM_128_64>>>(
        vin, 0, 512,  wv, 0, 512,  vp, 0, 512,  nullptr, bv, 1.0f, 512, nullptr);

    // 4. Per l-group: content scores (fp32 S slice) then pos-key+exp+rowsum
    //    S slice (33.5MB) stays L2-resident between the two launches.
    for (int g = 0; g < NGRP; g++) {
        const uint32_t* qpg = qp + (long long)g * LGRP * 4096;
        float* Sg   = Sbuf + (long long)g * LGRP * 1024;
        __half* Eg  = Ebuf + (long long)g * LGRP * 1024;

        // scores: S[b, l, s] = sum_d q k  (M = 128 l-rows, batch b)
        mma_gemm<128, 64, true, 0, 0, 0, false><<<dim3(16, 1, 64), 256, SM_128_64>>>(
            qpg, 64, 4096,  kp, 64, 4096,  Sg, (long long)1 << 20, 1024,
            nullptr, nullptr, 1.0f, 64, nullptr);

        // posk: E = exp(S + q@pos_k[l]^T), Z += rowsum  (M = 64 b-rows, batch l)
        mma_gemm<64, 128, true, 1, 0, 1, false><<<dim3(8, 1, LGRP), 256, SM_64_128>>>(
            qpg, 4096, 64,  pos_k + (long long)g * LGRP * 65536, 65536, 64,
            Eg, 1024, (long long)1 << 20,
            Sg, nullptr, 1.0f, 64, Zbuf + g * LGRP);
    }

    // 5. Content output (fp16 E x packed-fp16 vp, 2-term): O fp32 numerator
    mma_gemm<128, 64, false, 0, 1, 3, true><<<dim3(1, 8, 64), 256, SM_128_64>>>(
        Ebuf, (long long)1 << 20, 1024,  vp, 64, 4096,  Obuf, 64, 4096,
        nullptr, nullptr, 1.0f, 1024, nullptr);

    // 6. Pos-value + normalize: OP = packed_bf16( (O + E@pos_v[l]) / Z )
    mma_gemm<64, 64, false, 3, 1, 2, true><<<dim3(1, 1, 1024), 256, SM_64_64>>>(
        Ebuf, 1024, (long long)1 << 20,  pos_v, 65536, 64,  OP, 4096, 64,
        Obuf, nullptr, 1.0f, 1024, Zbuf);

    // 7. Output projection (packed OP x packed Wo)
    mma_gemm<128, 64, true, 0, 0, 0, false><<<dim3(8, 64, 1), 256, SM_128_64>>>(
        OP, 0, 512,  wo, 0, 512,  out, 0, 512,  nullptr, bo, 1.0f, 512, nullptr);

    // 8. Averaged weights
    avgw_kernel<<<dim3(1024, 8, 1), 256>>>(Ebuf, Zbuf, out + 4194304);
}

// round 10
// speedup vs baseline: 1.1330x; 1.1330x over previous
#include <cuda_runtime.h>
#include <cuda_bf16.h>
#include <cuda_fp16.h>
#include <cstdint>

// Problem constants
#define LQ 1024
#define SQ 1024
#define NBATCH 8
#define EDIM 512
#define BHEADS 64   // NBATCH * HHEADS

// ---------------- scratch (device globals; no allocations allowed) ----------
__device__ float  g_qp[LQ * NBATCH * EDIM];         // q proj fp32 (l, b, d)
__device__ float  g_kp[SQ * NBATCH * EDIM];         // k proj fp32
__device__ float  g_vp[SQ * NBATCH * EDIM];         // v proj fp32
__device__ __half g_P[67108864];                    // pos-score term fp16 (b,l,s)
__device__ __half g_E[67108864];                    // exp scores fp16 (b,l,s)
__device__ float  g_Z[BHEADS * LQ];                 // row sums
__device__ float  g_O[LQ * NBATCH * EDIM];          // numerator fp32 (l, b*64+d)

// =================== helpers ================================================
__device__ __forceinline__ uint32_t smem_u32(const void* p) {
    uint32_t a;
    asm("{ .reg .u64 t; cvta.to.shared.u64 t, %1; cvt.u32.u64 %0, t; }" : "=r"(a) : "l"(p));
    return a;
}
__device__ __forceinline__ void ldsm_x4(uint32_t* r, uint32_t addr) {
    asm volatile("ldmatrix.sync.aligned.m8n8.x4.shared.b16 {%0,%1,%2,%3}, [%4];"
        : "=r"(r[0]), "=r"(r[1]), "=r"(r[2]), "=r"(r[3]) : "r"(addr));
}
__device__ __forceinline__ void mma_bf16(float* c, const uint32_t* a, const uint32_t* b) {
    asm volatile(
        "mma.sync.aligned.m16n8k16.row.col.f32.bf16.bf16.f32 "
        "{%0,%1,%2,%3}, {%4,%5,%6,%7}, {%8,%9}, {%0,%1,%2,%3};"
        : "+f"(c[0]), "+f"(c[1]), "+f"(c[2]), "+f"(c[3])
        : "r"(a[0]), "r"(a[1]), "r"(a[2]), "r"(a[3]), "r"(b[0]), "r"(b[1]));
}
__device__ __forceinline__ void mma_f16(float* c, const uint32_t* a, const uint32_t* b) {
    asm volatile(
        "mma.sync.aligned.m16n8k16.row.col.f32.f16.f16.f32 "
        "{%0,%1,%2,%3}, {%4,%5,%6,%7}, {%8,%9}, {%0,%1,%2,%3};"
        : "+f"(c[0]), "+f"(c[1]), "+f"(c[2]), "+f"(c[3])
        : "r"(a[0]), "r"(a[1]), "r"(a[2]), "r"(a[3]), "r"(b[0]), "r"(b[1]));
}
// fp32 pair -> bf16 (hi, lo) splits
__device__ __forceinline__ void split2b(float x, float y, uint32_t& hi, uint32_t& lo) {
    __nv_bfloat16 h0 = __float2bfloat16(x);
    __nv_bfloat16 h1 = __float2bfloat16(y);
    __nv_bfloat16 l0 = __float2bfloat16(x - __bfloat162float(h0));
    __nv_bfloat16 l1 = __float2bfloat16(y - __bfloat162float(h1));
    hi = (uint32_t)__bfloat16_as_ushort(h0) | ((uint32_t)__bfloat16_as_ushort(h1) << 16);
    lo = (uint32_t)__bfloat16_as_ushort(l0) | ((uint32_t)__bfloat16_as_ushort(l1) << 16);
}
__device__ __forceinline__ uint32_t hi2b(float x, float y) {
    return (uint32_t)__bfloat16_as_ushort(__float2bfloat16(x))
         | ((uint32_t)__bfloat16_as_ushort(__float2bfloat16(y)) << 16);
}
__device__ __forceinline__ void split2h(float x, float y, uint32_t& hi, uint32_t& lo) {
    __half h0 = __float2half_rn(x);
    __half h1 = __float2half_rn(y);
    __half l0 = __float2half_rn(x - __half2float(h0));
    __half l1 = __float2half_rn(y - __half2float(h1));
    hi = (uint32_t)__half_as_ushort(h0) | ((uint32_t)__half_as_ushort(h1) << 16);
    lo = (uint32_t)__half_as_ushort(l0) | ((uint32_t)__half_as_ushort(l1) << 16);
}

// =================== HMMA strided batched GEMM ===============================
// C[z][m][n] = epilogue( sum_k A(m,k)*B(n,k) )
// A(m,k) = A[z*aBS + m*aRS + k]   (k contiguous; fp32 if ASPLIT else fp16 exact)
// B fp32: BKFAST ? B[z*bBS + n*bS + k] : B[z*bBS + k*bS + n]
// C at    C[z*cBS + m*cRS + n]
// MMA terms: aH*bH  [+ aH*bL if BSPLIT]  [+ aL*bH if ASPLIT]
// EPI: 0 = fp32 C = alpha*(acc+bias)
//      2 = DIVZ: fp32 C = (acc + Cold) / Zp[m*1024+z]   (Cold = C itself)
//      6 = EXPZ: e = exp(acc + CinH[...]); fp16 e -> C; atomicAdd Zp[z*1024+m]
//      7 = fp16 C = acc
// 256 threads = 8 warps (4m x 2n). BK=32. Double-buffered. 2 CTAs/SM.
template<int BM, int BN, bool BKFAST, int EPI, bool ASPLIT, bool BSPLIT, bool F16MMA>
__global__ __launch_bounds__(256, 2)
void mma_gemm(const void* __restrict__ Ap, long long aBS, long long aRS,
              const float* __restrict__ B, long long bBS, long long bS,
              void* __restrict__ Cp, long long cBS, long long cRS,
              const void* __restrict__ Cin,
              const float* __restrict__ bias, float alpha,
              int K, float* __restrict__ Zp)
{
    constexpr int MT    = BM / 64;
    constexpr int NTL   = BN / 16;
    constexpr int NPAIR = NTL / 2;
    constexpr int ROWB  = 144;
    constexpr int STG   = (BM + BN) * ROWB;
    constexpr int AREG  = BM * 16 / 256;             // 8B (fp32x2) or 4B (fp16x2) units
    constexpr int BREG2 = BKFAST ? BN * 16 / 256 : 1;
    constexpr int BREG1 = BKFAST ? 1 : BN * 32 / 256;

    extern __shared__ __align__(16) char smem[];

    const int tid  = threadIdx.x;
    const int wid  = tid >> 5;
    const int lane = tid & 31;
    const int wm   = wid >> 1;
    const int wn   = wid & 1;
    const int mat  = lane >> 3;
    const int rw   = lane & 7;

    const int tile_n = blockIdx.x * BN;
    const int tile_m = blockIdx.y * BM;
    const int z      = blockIdx.z;

    const float*  AzF = (const float*)Ap  + (long long)z * aBS + (long long)tile_m * aRS;
    const __half* AzH = (const __half*)Ap + (long long)z * aBS + (long long)tile_m * aRS;
    const float*  Bz  = B + (long long)z * bBS;

    float acc[MT][NTL][4];
#pragma unroll
    for (int i = 0; i < MT; i++)
#pragma unroll
        for (int j = 0; j < NTL; j++)
#pragma unroll
            for (int q = 0; q < 4; q++) acc[i][j][q] = 0.0f;

    const uint32_t s_u = smem_u32(smem);
    const uint32_t aAddr0 = s_u + (uint32_t)(wm * (BM / 4) + rw + (mat & 1) * 8) * ROWB
                                + (uint32_t)((mat >> 1) * 16);
    const uint32_t bAddr0 = s_u + (uint32_t)(BM * ROWB)
                                + (uint32_t)(wn * (BN / 2) + rw + (mat >> 1) * 8) * ROWB
                                + (uint32_t)((mat & 1) * 16);

    float2   aRegF[ASPLIT ? AREG : 1];
    uint32_t aRegH[ASPLIT ? 1 : AREG];
    float2   bReg2[BREG2];
    float    bReg1[BREG1];

    auto ldgA = [&](int ch) {
        if (ASPLIT) {
            const float* p = AzF + (ch << 5);
#pragma unroll
            for (int j = 0; j < AREG; j++) {
                int i = tid + j * 256;
                int k2 = i & 15, r = i >> 4;
                aRegF[j] = *reinterpret_cast<const float2*>(p + (long long)r * aRS + k2 * 2);
            }
        } else {
            const __half* p = AzH + (ch << 5);
#pragma unroll
            for (int j = 0; j < AREG; j++) {
                int i = tid + j * 256;
                int k2 = i & 15, r = i >> 4;
                aRegH[j] = *reinterpret_cast<const uint32_t*>(p + (long long)r * aRS + k2 * 2);
            }
        }
    };
    auto stsA = [&](int st) {
        char* base = smem + st * STG;
#pragma unroll
        for (int j = 0; j < AREG; j++) {
            int i = tid + j * 256;
            int k2 = i & 15, r = i >> 4;
            char* rp = base + r * ROWB + k2 * 4;
            if (ASPLIT) {
                uint32_t hi, lo;
                split2b(aRegF[j].x, aRegF[j].y, hi, lo);
                *reinterpret_cast<uint32_t*>(rp)      = hi;
                *reinterpret_cast<uint32_t*>(rp + 64) = lo;
            } else {
                *reinterpret_cast<uint32_t*>(rp) = aRegH[j];
            }
        }
    };
    auto ldgB = [&](int ch) {
        if (BKFAST) {
            const float* p = Bz + (long long)tile_n * bS + (ch << 5);
#pragma unroll
            for (int j = 0; j < BREG2; j++) {
                int i = tid + j * 256;
                int k2 = i & 15, r = i >> 4;
                bReg2[j] = *reinterpret_cast<const float2*>(p + (long long)r * bS + k2 * 2);
            }
        } else {
            const float* p = Bz + tile_n + (long long)(ch << 5) * bS;
#pragma unroll
            for (int j = 0; j < BREG1; j++) {
                int i = tid + j * 256;
                int n = i & (BN - 1), k = i / BN;
                bReg1[j] = p[(long long)k * bS + n];
            }
        }
    };
    auto stsB = [&](int st) {
        char* base = smem + st * STG + BM * ROWB;
        if (BKFAST) {
#pragma unroll
            for (int j = 0; j < BREG2; j++) {
                int i = tid + j * 256;
                int k2 = i & 15, r = i >> 4;
                char* rp = base + r * ROWB + k2 * 4;
                if (BSPLIT) {
                    uint32_t hi, lo;
                    if (F16MMA) split2h(bReg2[j].x, bReg2[j].y, hi, lo);
                    else        split2b(bReg2[j].x, bReg2[j].y, hi, lo);
                    *reinterpret_cast<uint32_t*>(rp)      = hi;
                    *reinterpret_cast<uint32_t*>(rp + 64) = lo;
                } else {
                    uint32_t hi;
                    if (F16MMA) {
                        __half2 h2 = __floats2half2_rn(bReg2[j].x, bReg2[j].y);
                        hi = *reinterpret_cast<uint32_t*>(&h2);
                    } else {
                        hi = hi2b(bReg2[j].x, bReg2[j].y);
                    }
                    *reinterpret_cast<uint32_t*>(rp) = hi;
                }
            }
        } else {
#pragma unroll
            for (int j = 0; j < BREG1; j++) {
                int i = tid + j * 256;
                int n = i & (BN - 1), k = i / BN;
                float v = bReg1[j];
                char* rp = base + n * ROWB + k * 2;
                if (F16MMA) {
                    __half hh = __float2half_rn(v);
                    *reinterpret_cast<unsigned short*>(rp) = __half_as_ushort(hh);
                    if (BSPLIT) {
                        __half ll = __float2half_rn(v - __half2float(hh));
                        *reinterpret_cast<unsigned short*>(rp + 64) = __half_as_ushort(ll);
                    }
                } else {
                    __nv_bfloat16 hh = __float2bfloat16(v);
                    *reinterpret_cast<unsigned short*>(rp) = __bfloat16_as_ushort(hh);
                    if (BSPLIT) {
                        __nv_bfloat16 ll = __float2bfloat16(v - __bfloat162float(hh));
                        *reinterpret_cast<unsigned short*>(rp + 64) = __bfloat16_as_ushort(ll);
                    }
                }
            }
        }
    };
    auto compute = [&](int st) {
        const uint32_t off = (uint32_t)(st * STG);
#pragma unroll
        for (int ks = 0; ks < 2; ks++) {
            uint32_t aH[MT][4], aL[MT][4];
#pragma unroll
            for (int mt = 0; mt < MT; mt++) {
                uint32_t ad = aAddr0 + off + (uint32_t)(mt * 16 * ROWB) + (uint32_t)(ks * 32);
                ldsm_x4(aH[mt], ad);
                if (ASPLIT) ldsm_x4(aL[mt], ad + 64);
            }
            uint32_t bH[NTL][2], bL[NTL][2];
#pragma unroll
            for (int p = 0; p < NPAIR; p++) {
                uint32_t bd = bAddr0 + off + (uint32_t)(p * 16 * ROWB) + (uint32_t)(ks * 32);
                uint32_t t[4];
                ldsm_x4(t, bd);
                bH[2 * p][0] = t[0]; bH[2 * p][1] = t[1];
                bH[2 * p + 1][0] = t[2]; bH[2 * p + 1][1] = t[3];
                if (BSPLIT) {
                    ldsm_x4(t, bd + 64);
                    bL[2 * p][0] = t[0]; bL[2 * p][1] = t[1];
                    bL[2 * p + 1][0] = t[2]; bL[2 * p + 1][1] = t[3];
                }
            }
#pragma unroll
            for (int mt = 0; mt < MT; mt++)
#pragma unroll
                for (int nt = 0; nt < NTL; nt++) {
                    if (F16MMA) {
                        mma_f16(acc[mt][nt], aH[mt], bH[nt]);
                        if (BSPLIT) mma_f16(acc[mt][nt], aH[mt], bL[nt]);
                        if (ASPLIT) mma_f16(acc[mt][nt], aL[mt], bH[nt]);
                    } else {
                        mma_bf16(acc[mt][nt], aH[mt], bH[nt]);
                        if (BSPLIT) mma_bf16(acc[mt][nt], aH[mt], bL[nt]);
                        if (ASPLIT) mma_bf16(acc[mt][nt], aL[mt], bH[nt]);
                    }
                }
        }
    };

    const int nch = K >> 5;
    ldgA(0); ldgB(0);
    stsA(0); stsB(0);
    __syncthreads();
    for (int ch = 0; ch < nch; ch++) {
        const bool more = (ch + 1 < nch);
        if (more) { ldgA(ch + 1); ldgB(ch + 1); }
        compute(ch & 1);
        if (more) {
            stsA((ch + 1) & 1); stsB((ch + 1) & 1);
            __syncthreads();
        }
    }

    // ---- epilogue ----
#pragma unroll
    for (int mt = 0; mt < MT; mt++) {
        int m0 = tile_m + wm * (BM / 4) + mt * 16 + (lane >> 2);
#pragma unroll
        for (int half = 0; half < 2; half++) {
            int m = m0 + half * 8;
            const long long coff = (long long)z * cBS + (long long)m * cRS;
            if (EPI == 6) {
                const __half* cinrow = (const __half*)Cin + coff;
                __half* erow = (__half*)Cp + coff;
                float rowsum = 0.0f;
#pragma unroll
                for (int nt = 0; nt < NTL; nt++) {
                    int n = tile_n + wn * (BN / 2) + nt * 8 + (lane & 3) * 2;
                    float2 o = __half22float2(*reinterpret_cast<const __half2*>(cinrow + n));
                    float ex = __expf(acc[mt][nt][half * 2]     + o.x);
                    float ey = __expf(acc[mt][nt][half * 2 + 1] + o.y);
                    *reinterpret_cast<__half2*>(erow + n) = __floats2half2_rn(ex, ey);
                    rowsum += ex + ey;
                }
                rowsum += __shfl_xor_sync(0xffffffffu, rowsum, 1);
                rowsum += __shfl_xor_sync(0xffffffffu, rowsum, 2);
                if ((lane & 3) == 0)
                    atomicAdd(&Zp[(long long)z * 1024 + m], rowsum);
            } else if (EPI == 7) {
                __half* crow = (__half*)Cp + coff;
#pragma unroll
                for (int nt = 0; nt < NTL; nt++) {
                    int n = tile_n + wn * (BN / 2) + nt * 8 + (lane & 3) * 2;
                    *reinterpret_cast<__half2*>(crow + n) =
                        __floats2half2_rn(acc[mt][nt][half * 2], acc[mt][nt][half * 2 + 1]);
                }
            } else if (EPI == 2) {
                float* crow = (float*)Cp + coff;
                float invZ = 1.0f / Zp[(long long)m * 1024 + z];
#pragma unroll
                for (int nt = 0; nt < NTL; nt++) {
                    int n = tile_n + wn * (BN / 2) + nt * 8 + (lane & 3) * 2;
                    float2 o = *reinterpret_cast<float2*>(crow + n);
                    float2 v;
                    v.x = (acc[mt][nt][half * 2]     + o.x) * invZ;
                    v.y = (acc[mt][nt][half * 2 + 1] + o.y) * invZ;
                    *reinterpret_cast<float2*>(crow + n) = v;
                }
            } else {
                float* crow = (float*)Cp + coff;
#pragma unroll
                for (int nt = 0; nt < NTL; nt++) {
                    int n = tile_n + wn * (BN / 2) + nt * 8 + (lane & 3) * 2;
                    float vx = acc[mt][nt][half * 2];
                    float vy = acc[mt][nt][half * 2 + 1];
                    if (bias) { vx += bias[n]; vy += bias[n + 1]; }
                    vx *= alpha; vy *= alpha;
                    float2 v; v.x = vx; v.y = vy;
                    *reinterpret_cast<float2*>(crow + n) = v;
                }
            }
        }
    }
}

// =================== small kernels ===========================================
__global__ __launch_bounds__(256)
void zeroZ_kernel(float* __restrict__ Z)
{
    Z[blockIdx.x * 256 + threadIdx.x] = 0.0f;
}

__global__ __launch_bounds__(256)
void avgw_kernel(const __half* __restrict__ Ebuf, const float* __restrict__ Z,
                 float* __restrict__ out)
{
    int l = blockIdx.x;
    int n = blockIdx.y;
    __shared__ float invZ[8];
    if (threadIdx.x < 8)
        invZ[threadIdx.x] = 0.125f / Z[(n * 8 + threadIdx.x) * 1024 + l];
    __syncthreads();
    int s = threadIdx.x * 4;
    float4 acc = make_float4(0.f, 0.f, 0.f, 0.f);
#pragma unroll
    for (int h = 0; h < 8; h++) {
        const __half2* p = reinterpret_cast<const __half2*>(
            Ebuf + (((long long)(n * 8 + h)) << 20) + (long long)l * 1024 + s);
        float2 a = __half22float2(p[0]);
        float2 b = __half22float2(p[1]);
        float w = invZ[h];
        acc.x += a.x * w; acc.y += a.y * w; acc.z += b.x * w; acc.w += b.y * w;
    }
    *reinterpret_cast<float4*>(
        out + (((long long)n) << 20) + (long long)l * 1024 + s) = acc;
}

// =================== launch ==================================================
extern "C" void kernel_launch(void* const* d_in, const int* in_sizes, int n_in,
                              void* d_out, int out_size)
{
    const float* query = (const float*)d_in[0];
    const float* key   = (const float*)d_in[1];
    const float* value = (const float*)d_in[2];
    const float* pos_k = (const float*)d_in[3];
    const float* pos_v = (const float*)d_in[4];
    const float* Wq = (const float*)d_in[5];
    const float* bq = (const float*)d_in[6];
    const float* Wk = (const float*)d_in[7];
    const float* bk = (const float*)d_in[8];
    const float* Wv = (const float*)d_in[9];
    const float* bv = (const float*)d_in[10];
    const float* Wo = (const float*)d_in[11];
    const float* bo = (const float*)d_in[12];
    float* out = (float*)d_out;

    float *qp, *kp, *vp, *Zbuf, *Obuf;
    __half *Pbuf, *Ebuf;
    cudaGetSymbolAddress((void**)&qp,   g_qp);
    cudaGetSymbolAddress((void**)&kp,   g_kp);
    cudaGetSymbolAddress((void**)&vp,   g_vp);
    cudaGetSymbolAddress((void**)&Pbuf, g_P);
    cudaGetSymbolAddress((void**)&Ebuf, g_E);
    cudaGetSymbolAddress((void**)&Zbuf, g_Z);
    cudaGetSymbolAddress((void**)&Obuf, g_O);

    const int SM_128_64 = 2 * (128 + 64) * 144;   // 55296
    const int SM_64_128 = 2 * (64 + 128) * 144;   // 55296
    const int SM_64_64  = 2 * (64 + 64) * 144;    // 36864

    // template instances
    //  proj / outproj: ASPLIT, BSPLIT, bf16, BKFAST, EPI 0
    cudaFuncSetAttribute((const void*)mma_gemm<128, 64, true, 0, true, true, false>,
        cudaFuncAttributeMaxDynamicSharedMemorySize, SM_128_64);
    //  posk: ASPLIT, B hi-only, bf16, BKFAST, EPI 7 (fp16 P out)
    cudaFuncSetAttribute((const void*)mma_gemm<64, 128, true, 7, true, false, false>,
        cudaFuncAttributeMaxDynamicSharedMemorySize, SM_64_128);
    //  scores: ASPLIT, BSPLIT, bf16, BKFAST, EPI 6 (exp + Z)
    cudaFuncSetAttribute((const void*)mma_gemm<128, 64, true, 6, true, true, false>,
        cudaFuncAttributeMaxDynamicSharedMemorySize, SM_128_64);
    //  contout: A fp16 exact, BSPLIT, f16, n-contig, EPI 0
    cudaFuncSetAttribute((const void*)mma_gemm<128, 64, false, 0, false, true, true>,
        cudaFuncAttributeMaxDynamicSharedMemorySize, SM_128_64);
    //  posv: A fp16 exact, B hi-only, f16, n-contig, EPI 2
    cudaFuncSetAttribute((const void*)mma_gemm<64, 64, false, 2, false, false, true>,
        cudaFuncAttributeMaxDynamicSharedMemorySize, SM_64_64);

    // 0. Zero softmax denominators
    zeroZ_kernel<<<256, 256>>>(Zbuf);

    // 1-3. Projections: (8192 x 512) @ W^T + b  -> fp32
    mma_gemm<128, 64, true, 0, true, true, false><<<dim3(8, 64, 1), 256, SM_128_64>>>(
        query, 0, 512,  Wq, 0, 512,  qp, 0, 512,  nullptr, bq, 0.125f, 512, nullptr);
    mma_gemm<128, 64, true, 0, true, true, false><<<dim3(8, 64, 1), 256, SM_128_64>>>(
        key,   0, 512,  Wk, 0, 512,  kp, 0, 512,  nullptr, bk, 1.0f, 512, nullptr);
    mma_gemm<128, 64, true, 0, true, true, false><<<dim3(8, 64, 1), 256, SM_128_64>>>(
        value, 0, 512,  Wv, 0, 512,  vp, 0, 512,  nullptr, bv, 1.0f, 512, nullptr);

    // 4. Pos-key term first (batch l=1024, 2-term): P[b,l,s] = fp16( q[l]@pos_k[l]^T )
    mma_gemm<64, 128, true, 7, true, false, false><<<dim3(8, 1, 1024), 256, SM_64_128>>>(
        qp, 4096, 64,  pos_k, 65536, 64,  Pbuf, 1024, (long long)1 << 20,
        nullptr, nullptr, 1.0f, 64, nullptr);

    // 5. Content scores + exp + rowsum (batch b=64, 3-term):
    //    E[b,l,s] = fp16( exp( q@k^T + P ) ); Z[b,l] += rowsums
    mma_gemm<128, 64, true, 6, true, true, false><<<dim3(16, 8, 64), 256, SM_128_64>>>(
        qp, 64, 4096,  kp, 64, 4096,  Ebuf, (long long)1 << 20, 1024,
        Pbuf, nullptr, 1.0f, 64, Zbuf);

    // 6. Content output (batch b=64, fp16 E x split-fp16 v, 2-term): fp32 numerator
    mma_gemm<128, 64, false, 0, false, true, true><<<dim3(1, 8, 64), 256, SM_128_64>>>(
        Ebuf, (long long)1 << 20, 1024,  vp, 64, 4096,  Obuf, 64, 4096,
        nullptr, nullptr, 1.0f, 1024, nullptr);

    // 7. Pos-value + normalize (batch l=1024, fp16 E x hi-fp16 pos_v, 1-term):
    //    O = (O_old + E@pos_v[l]) / Z
    mma_gemm<64, 64, false, 2, false, false, true><<<dim3(1, 1, 1024), 256, SM_64_64>>>(
        Ebuf, 1024, (long long)1 << 20,  pos_v, 65536, 64,  Obuf, 4096, 64,
        nullptr, nullptr, 1.0f, 1024, Zbuf);

    // 8. Output projection
    mma_gemm<128, 64, true, 0, true, true, false><<<dim3(8, 64, 1), 256, SM_128_64>>>(
        Obuf, 0, 512,  Wo, 0, 512,  out, 0, 512,  nullptr, bo, 1.0f, 512, nullptr);

    // 9. Averaged weights
    avgw_kernel<<<dim3(1024, 8, 1), 256>>>(Ebuf, Zbuf, out + 4194304);
}